// round 3
// baseline (speedup 1.0000x reference)
#include <cuda_runtime.h>
#include <math.h>

// Problem dims
#define BEFF   1920     // effective batch = B*T/W
#define HID    512
#define FEAT   25
#define ZDIM   256
#define MDIM   512
#define NC3D   58
#define WSTEPS 50
#define GATES  2048     // 4*HID
#define NROWS  96000    // B*T

// ---------------- device scratch (static: no allocations allowed) -------------
__device__ float g_h[2][BEFF * HID];
__device__ float g_c[2][BEFF * HID];
__device__ float g_hy[BEFF * HID];
__device__ float g_base[BEFF * GATES];     // precomputed h_y @ dec_Wih[:, :512].T + biases
__device__ float g_m1[BEFF * MDIM];
__device__ float g_m2[BEFF * MDIM];
__device__ float g_encb[GATES];            // enc_bih + enc_bhh
__device__ float g_zero32[32];             // stays zero (never written)

// ---------------- helpers ----------------------------------------------------
__device__ __forceinline__ float sigf(float x) {
    return 1.0f / (1.0f + __expf(-x));
}

__global__ void zero2_kernel(float* __restrict__ a, float* __restrict__ b, int n) {
    for (int i = blockIdx.x * blockDim.x + threadIdx.x; i < n; i += gridDim.x * blockDim.x) {
        a[i] = 0.0f;
        b[i] = 0.0f;
    }
}

__global__ void addvec_kernel(const float* __restrict__ x, const float* __restrict__ y,
                              float* __restrict__ o, int n) {
    int i = blockIdx.x * blockDim.x + threadIdx.x;
    if (i < n) o[i] = x[i] + y[i];
}

// ---------------- generic tiled GEMM: C[n,m] = act(b1[m]+b2[m] + sum_k A[n,k]*W[m,k])
// Tile 64x64, TK=16, 256 threads, 16 acc/thread. Grid covers M exactly via blockIdx.y
// (ragged N guarded, ragged K guarded & zero-filled).
template <int ACT>  // 0 = none, 1 = tanh
__global__ void __launch_bounds__(256)
gemm_kernel(const float* __restrict__ A, int lda,
            const float* __restrict__ W, int ldw,
            const float* __restrict__ b1, const float* __restrict__ b2,
            float* __restrict__ C, int ldc,
            int N, int K) {
    __shared__ __align__(16) float As[16][68];
    __shared__ __align__(16) float Bs[16][68];

    const int tid = threadIdx.x;
    const int tx = tid & 15;        // m group
    const int ty = tid >> 4;        // n group
    const int n0 = blockIdx.x * 64;
    const int m0 = blockIdx.y * 64;
    const int lk = tid & 15;        // k lane for loads
    const int lr = tid >> 4;        // row lane for loads

    float acc[4][4] = {};

    for (int k0 = 0; k0 < K; k0 += 16) {
        const int k = k0 + lk;
        const bool kv = (k < K);
#pragma unroll
        for (int i = 0; i < 4; i++) {
            const int row = lr + 16 * i;
            As[lk][row] = kv ? A[(n0 + row) * lda + k] : 0.0f;
            const int m = m0 + row;
            Bs[lk][row] = (kv && m < N) ? W[m * ldw + k] : 0.0f;
        }
        __syncthreads();
#pragma unroll
        for (int kk = 0; kk < 16; kk++) {
            float4 a4 = *(const float4*)&As[kk][ty * 4];
            float4 b4 = *(const float4*)&Bs[kk][tx * 4];
            float av[4] = {a4.x, a4.y, a4.z, a4.w};
            float bv[4] = {b4.x, b4.y, b4.z, b4.w};
#pragma unroll
            for (int r = 0; r < 4; r++)
#pragma unroll
                for (int c2 = 0; c2 < 4; c2++)
                    acc[r][c2] += av[r] * bv[c2];
        }
        __syncthreads();
    }

#pragma unroll
    for (int r = 0; r < 4; r++) {
        const int n = n0 + ty * 4 + r;
#pragma unroll
        for (int c2 = 0; c2 < 4; c2++) {
            const int m = m0 + tx * 4 + c2;
            if (m < N) {
                float v = acc[r][c2];
                if (b1) v += b1[m];
                if (b2) v += b2[m];
                if (ACT == 1) v = tanhf(v);
                C[n * ldc + m] = v;
            }
        }
    }
}

// ---------------- fused LSTM step -------------------------------------------
// Each CTA: 64 batch rows x 64 h-columns x all 4 gates.
// gates[n, g*512+j] = addm[n*ldadd + g*512+j]
//                   + sum_{k<512} h_src[n,k] * Whh[(g*512+j), k]
//                   + sum_{k<25}  A2[n*lda2 + k] * W2[(g*512+j)*ldw2 + k]
// Then the LSTM cell update is applied in the epilogue (i,f,g,o torch order).
__global__ void __launch_bounds__(256)
lstm_step_kernel(const float* __restrict__ h_src, const float* __restrict__ c_src,
                 float* __restrict__ h_dst, float* __restrict__ c_dst,
                 const float* __restrict__ Whh, int ldwhh,
                 const float* __restrict__ A2, int lda2,
                 const float* __restrict__ W2, int ldw2,
                 const float* __restrict__ addm, int ldadd) {
    __shared__ __align__(16) float Hs[16][68];
    __shared__ __align__(16) float Gs[4][16][68];

    const int tid = threadIdx.x;
    const int tx = tid & 15;   // j group
    const int ty = tid >> 4;   // n group
    const int n0 = blockIdx.x * 64;
    const int j0 = blockIdx.y * 64;
    const int lk = tid & 15;
    const int lr = tid >> 4;

    float acc[4][4][4] = {};   // [gate][n][j]

    // ---- recurrent part: K = 512 over h ----
    for (int k0 = 0; k0 < 512; k0 += 16) {
#pragma unroll
        for (int i = 0; i < 4; i++) {
            const int row = lr + 16 * i;
            Hs[lk][row] = h_src[(n0 + row) * HID + k0 + lk];
#pragma unroll
            for (int g = 0; g < 4; g++)
                Gs[g][lk][row] = Whh[(g * HID + j0 + row) * ldwhh + k0 + lk];
        }
        __syncthreads();
#pragma unroll
        for (int kk = 0; kk < 16; kk++) {
            float4 h4 = *(const float4*)&Hs[kk][ty * 4];
            float hv[4] = {h4.x, h4.y, h4.z, h4.w};
#pragma unroll
            for (int g = 0; g < 4; g++) {
                float4 w4 = *(const float4*)&Gs[g][kk][tx * 4];
                float wv[4] = {w4.x, w4.y, w4.z, w4.w};
#pragma unroll
                for (int r = 0; r < 4; r++)
#pragma unroll
                    for (int c2 = 0; c2 < 4; c2++)
                        acc[g][r][c2] += hv[r] * wv[c2];
            }
        }
        __syncthreads();
    }

    // ---- small input part: K = 25 ----
    for (int k0 = 0; k0 < FEAT; k0 += 16) {
        const int k = k0 + lk;
        const bool kv = (k < FEAT);
#pragma unroll
        for (int i = 0; i < 4; i++) {
            const int row = lr + 16 * i;
            Hs[lk][row] = kv ? A2[(n0 + row) * lda2 + k] : 0.0f;
#pragma unroll
            for (int g = 0; g < 4; g++)
                Gs[g][lk][row] = kv ? W2[(g * HID + j0 + row) * ldw2 + k] : 0.0f;
        }
        __syncthreads();
#pragma unroll
        for (int kk = 0; kk < 16; kk++) {
            float4 h4 = *(const float4*)&Hs[kk][ty * 4];
            float hv[4] = {h4.x, h4.y, h4.z, h4.w};
#pragma unroll
            for (int g = 0; g < 4; g++) {
                float4 w4 = *(const float4*)&Gs[g][kk][tx * 4];
                float wv[4] = {w4.x, w4.y, w4.z, w4.w};
#pragma unroll
                for (int r = 0; r < 4; r++)
#pragma unroll
                    for (int c2 = 0; c2 < 4; c2++)
                        acc[g][r][c2] += hv[r] * wv[c2];
            }
        }
        __syncthreads();
    }

    // ---- LSTM cell update epilogue ----
#pragma unroll
    for (int r = 0; r < 4; r++) {
        const int n = n0 + ty * 4 + r;
#pragma unroll
        for (int c2 = 0; c2 < 4; c2++) {
            const int j = j0 + tx * 4 + c2;
            const int ab = n * ldadd;
            float iv = acc[0][r][c2] + addm[ab + j];
            float fv = acc[1][r][c2] + addm[ab + 512 + j];
            float gv = acc[2][r][c2] + addm[ab + 1024 + j];
            float ov = acc[3][r][c2] + addm[ab + 1536 + j];
            float cold = c_src[n * HID + j];
            float cn = sigf(fv) * cold + sigf(iv) * tanhf(gv);
            float hn = sigf(ov) * tanhf(cn);
            c_dst[n * HID + j] = cn;
            h_dst[n * HID + j] = hn;
        }
    }
}

// ---------------- fused 3DMM head --------------------------------------------
// coeff[r, m] = b2[m] + sum_j tanh( b1[j] + sum_k pred[r,k]*C1[j,k] ) * C2[m,j]
// One CTA handles 64 rows. Hidden is computed in 64-column chunks held in smem;
// the matching 64x25 slice of C1 is staged per chunk; C2 rows stream from L2.
// smem: sP 6.7KB + sC1c 6.7KB + sHid 16KB = ~29KB  (< 48KB static limit)
__global__ void __launch_bounds__(256)
head3dmm_kernel(const float* __restrict__ pred,   // [NROWS, 25]
                const float* __restrict__ C1, const float* __restrict__ b1,
                const float* __restrict__ C2, const float* __restrict__ b2,
                float* __restrict__ coeff) {      // [NROWS, 58]
    __shared__ __align__(16) float sP[64][FEAT + 1];     // pred rows
    __shared__ __align__(16) float sC1c[64][FEAT + 1];   // C1 chunk (64 j-rows x 25)
    __shared__ __align__(16) float sHid[64][64];         // hidden chunk

    const int tid = threadIdx.x;
    const int r0 = blockIdx.x * 64;

    // load pred rows into smem: 64 x 25
    for (int i = tid; i < 64 * FEAT; i += 256) {
        sP[i / FEAT][i % FEAT] = pred[(r0 + i / FEAT) * FEAT + i % FEAT];
    }

    // thread t: row = t>>2 (64 rows), l4 = t&3; covers m = l4, l4+4, ... (<58)
    const int row = tid >> 2;
    const int l4 = tid & 3;
    float acc[15];
#pragma unroll
    for (int q = 0; q < 15; q++) acc[q] = 0.0f;

    // process hidden columns in chunks of 64
    for (int jc = 0; jc < HID; jc += 64) {
        __syncthreads();
        // stage C1 chunk: rows jc..jc+63, 25 cols
        for (int i = tid; i < 64 * FEAT; i += 256) {
            sC1c[i / FEAT][i % FEAT] = C1[(jc + i / FEAT) * FEAT + i % FEAT];
        }
        __syncthreads();
        // compute hidden[row][jc + l4*16 + jj] for jj in [0,16)
#pragma unroll
        for (int jj = 0; jj < 16; jj++) {
            const int jl = l4 * 16 + jj;
            float v = b1[jc + jl];
#pragma unroll
            for (int k = 0; k < FEAT; k++)
                v += sP[row][k] * sC1c[jl][k];
            sHid[row][jl] = tanhf(v);
        }
        __syncthreads();
        // accumulate: acc[q] += sum_{jj<64} hid[row][jj] * C2[m*HID + jc + jj]
        for (int q = 0; q < 15; q++) {
            const int m = l4 + q * 4;
            if (m < NC3D) {
                float s = 0.0f;
                const float* c2r = C2 + m * HID + jc;
#pragma unroll
                for (int jj = 0; jj < 64; jj++)
                    s += sHid[row][jj] * c2r[jj];
                acc[q] += s;
            }
        }
    }

#pragma unroll
    for (int q = 0; q < 15; q++) {
        const int m = l4 + q * 4;
        if (m < NC3D)
            coeff[(r0 + row) * NC3D + m] = acc[q] + b2[m];
    }
}

// ---------------- host orchestration (graph-capturable) ----------------------
extern "C" void kernel_launch(void* const* d_in, const int* in_sizes, int n_in,
                              void* d_out, int out_size) {
    const float* em   = (const float*)d_in[0];   // listener_emotion (128,750,25)
    // d_in[1] listener_3dmm: unused by the reference computation
    const float* eWih = (const float*)d_in[2];
    const float* eWhh = (const float*)d_in[3];
    const float* ebih = (const float*)d_in[4];
    const float* ebhh = (const float*)d_in[5];
    const float* muW  = (const float*)d_in[6];
    const float* mub  = (const float*)d_in[7];
    const float* lvW  = (const float*)d_in[8];
    const float* lvb  = (const float*)d_in[9];
    const float* zW   = (const float*)d_in[10];
    const float* zb   = (const float*)d_in[11];
    const float* dWih = (const float*)d_in[12];
    const float* dWhh = (const float*)d_in[13];
    const float* dbih = (const float*)d_in[14];
    const float* dbhh = (const float*)d_in[15];
    const float* m1W  = (const float*)d_in[16];
    const float* m1b  = (const float*)d_in[17];
    const float* m2W  = (const float*)d_in[18];
    const float* m2b  = (const float*)d_in[19];
    const float* oW   = (const float*)d_in[20];
    const float* ob   = (const float*)d_in[21];
    const float* c1W  = (const float*)d_in[22];
    const float* c1b  = (const float*)d_in[23];
    const float* c2W  = (const float*)d_in[24];
    const float* c2b  = (const float*)d_in[25];

    float* out   = (float*)d_out;
    float* pred  = out;                          // 96000*25
    float* coeff = out + 2400000;                // 96000*58
    float* mu    = out + 2400000 + 5568000;      // 1920*256
    float* lv    = mu + 491520;                  // 1920*256

    float *hbase, *cbase, *hy, *base, *m1, *m2, *encb, *z32;
    cudaGetSymbolAddress((void**)&hbase, g_h);
    cudaGetSymbolAddress((void**)&cbase, g_c);
    cudaGetSymbolAddress((void**)&hy,    g_hy);
    cudaGetSymbolAddress((void**)&base,  g_base);
    cudaGetSymbolAddress((void**)&m1,    g_m1);
    cudaGetSymbolAddress((void**)&m2,    g_m2);
    cudaGetSymbolAddress((void**)&encb,  g_encb);
    cudaGetSymbolAddress((void**)&z32,   g_zero32);
    float* h0 = hbase;
    float* h1 = hbase + BEFF * HID;
    float* c0 = cbase;
    float* c1 = cbase + BEFF * HID;

    const dim3 blk(256);
    const dim3 gLSTM(30, 8);     // 1920/64 x 512/64 (x4 gates per CTA)

    // init
    zero2_kernel<<<256, blk>>>(h0, c0, BEFF * HID);
    addvec_kernel<<<8, blk>>>(ebih, ebhh, encb, GATES);

    // ---- encoder: 50 sequential LSTM steps ----
    for (int t = 0; t < WSTEPS; t++) {
        const float* hs = (t & 1) ? h1 : h0;
        const float* cs = (t & 1) ? c1 : c0;
        float* hd = (t & 1) ? h0 : h1;
        float* cd = (t & 1) ? c0 : c1;
        lstm_step_kernel<<<gLSTM, blk>>>(hs, cs, hd, cd,
                                         eWhh, HID,
                                         em + t * FEAT, WSTEPS * FEAT,   // x_t, row stride 1250
                                         eWih, FEAT,
                                         encb, 0);
    }
    // final h_x lives in h0 (50 steps, even count)

    // ---- latent head ----
    gemm_kernel<0><<<dim3(30, 4), blk>>>(h0, HID, muW, HID, mub, nullptr, mu, ZDIM, ZDIM, HID);
    gemm_kernel<0><<<dim3(30, 4), blk>>>(h0, HID, lvW, HID, lvb, nullptr, lv, ZDIM, ZDIM, HID);
    gemm_kernel<0><<<dim3(30, 8), blk>>>(mu, ZDIM, zW, ZDIM, zb, nullptr, hy, HID, HID, ZDIM);
    // dec_base = h_y @ dec_Wih[:, :512].T + dec_bih + dec_bhh   (hoisted out of loop)
    gemm_kernel<0><<<dim3(30, 32), blk>>>(hy, HID, dWih, HID + FEAT, dbih, dbhh,
                                          base, GATES, GATES, HID);

    // reset state for decoder
    zero2_kernel<<<256, blk>>>(h0, c0, BEFF * HID);

    // ---- decoder: 50 sequential steps ----
    for (int t = 0; t < WSTEPS; t++) {
        const float* hs = (t & 1) ? h1 : h0;
        const float* cs = (t & 1) ? c1 : c0;
        float* hd = (t & 1) ? h0 : h1;
        float* cd = (t & 1) ? c0 : c1;
        const float* yprev = (t == 0) ? z32 : (pred + (t - 1) * FEAT);
        const int ldy = (t == 0) ? 0 : WSTEPS * FEAT;
        lstm_step_kernel<<<gLSTM, blk>>>(hs, cs, hd, cd,
                                         dWhh, HID,
                                         yprev, ldy,
                                         dWih + HID, HID + FEAT,
                                         base, GATES);
        gemm_kernel<1><<<dim3(30, 8), blk>>>(hd, HID, m1W, MDIM, m1b, nullptr, m1, MDIM, MDIM, HID);
        gemm_kernel<1><<<dim3(30, 8), blk>>>(m1, MDIM, m2W, MDIM, m2b, nullptr, m2, MDIM, MDIM, MDIM);
        gemm_kernel<0><<<dim3(30, 1), blk>>>(m2, MDIM, oW, MDIM, ob, nullptr,
                                             pred + t * FEAT, WSTEPS * FEAT, FEAT, MDIM);
    }

    // ---- 3DMM head: fused, no global intermediate ----
    head3dmm_kernel<<<1500, blk>>>(pred, c1W, c1b, c2W, c2b, coeff);
}

// round 4
// speedup vs baseline: 1.1185x; 1.1185x over previous
#include <cuda_runtime.h>
#include <math.h>
#include <stdint.h>

// Problem dims
#define BEFF   1920     // effective batch = B*T/W
#define HID    512
#define FEAT   25
#define ZDIM   256
#define MDIM   512
#define NC3D   58
#define WSTEPS 50
#define GATES  2048     // 4*HID
#define NROWS  96000    // B*T

// ---------------- device scratch (static: no allocations allowed) -------------
__device__ float g_h[2][BEFF * HID];
__device__ float g_c[2][BEFF * HID];
__device__ float g_hy[BEFF * HID];
__device__ float g_base[BEFF * GATES];     // precomputed h_y @ dec_Wih[:, :512].T + biases
__device__ float g_m1[BEFF * MDIM];
__device__ float g_m2[BEFF * MDIM];
__device__ float g_encb[GATES];            // enc_bih + enc_bhh
__device__ float g_zero32[32];             // stays zero (never written)

// ---------------- helpers ----------------------------------------------------
__device__ __forceinline__ float sigf(float x) {
    return 1.0f / (1.0f + __expf(-x));
}
__device__ __forceinline__ uint32_t s2u(const void* p) {
    return (uint32_t)__cvta_generic_to_shared(p);
}
__device__ __forceinline__ void cpa4(uint32_t d, const void* s) {
    asm volatile("cp.async.ca.shared.global [%0], [%1], 4;" :: "r"(d), "l"(s));
}
__device__ __forceinline__ void cpa4p(uint32_t d, const void* s, int szbytes) {
    asm volatile("cp.async.ca.shared.global [%0], [%1], 4, %2;" :: "r"(d), "l"(s), "r"(szbytes));
}
__device__ __forceinline__ void cp_commit() { asm volatile("cp.async.commit_group;"); }
__device__ __forceinline__ void cp_wait0()  { asm volatile("cp.async.wait_group 0;"); }
__device__ __forceinline__ void cp_wait1()  { asm volatile("cp.async.wait_group 1;"); }

__global__ void zero2_kernel(float* __restrict__ a, float* __restrict__ b, int n) {
    for (int i = blockIdx.x * blockDim.x + threadIdx.x; i < n; i += gridDim.x * blockDim.x) {
        a[i] = 0.0f;
        b[i] = 0.0f;
    }
}

__global__ void addvec_kernel(const float* __restrict__ x, const float* __restrict__ y,
                              float* __restrict__ o, int n) {
    int i = blockIdx.x * blockDim.x + threadIdx.x;
    if (i < n) o[i] = x[i] + y[i];
}

// ---------------- generic tiled GEMM (cp.async double-buffered) --------------
// C[n,m] = act(b1[m]+b2[m] + sum_k A[n,k]*W[m,k]); tile 64x64, TK=16.
// Requirements: K % 16 == 0, grid.x*64 == #rows of A. N may be ragged (guarded).
template <int ACT>  // 0 = none, 1 = tanh
__global__ void __launch_bounds__(256, 2)
gemm_kernel(const float* __restrict__ A, int lda,
            const float* __restrict__ W, int ldw,
            const float* __restrict__ b1, const float* __restrict__ b2,
            float* __restrict__ C, int ldc,
            int N, int K) {
    __shared__ __align__(16) float As[2][16][68];
    __shared__ __align__(16) float Bs[2][16][68];

    const int tid = threadIdx.x;
    const int tx = tid & 15;        // m group
    const int ty = tid >> 4;        // n group
    const int n0 = blockIdx.x * 64;
    const int m0 = blockIdx.y * 64;
    const int lk = tid & 15;        // k lane for loads
    const int lr = tid >> 4;        // row lane for loads

    float acc[4][4] = {};
    const int nch = K >> 4;

    auto issue = [&](int k0, int b) {
#pragma unroll
        for (int i = 0; i < 4; i++) {
            const int row = lr + 16 * i;
            cpa4(s2u(&As[b][lk][row]), &A[(n0 + row) * lda + k0 + lk]);
            const int m = m0 + row;
            const int mc = (m < N) ? m : 0;
            cpa4p(s2u(&Bs[b][lk][row]), &W[mc * ldw + k0 + lk], (m < N) ? 4 : 0);
        }
        cp_commit();
    };

    issue(0, 0);
    for (int c = 0; c < nch; c++) {
        if (c + 1 < nch) { issue((c + 1) * 16, (c + 1) & 1); cp_wait1(); }
        else             { cp_wait0(); }
        __syncthreads();
        const int p = c & 1;
#pragma unroll
        for (int kk = 0; kk < 16; kk++) {
            float4 a4 = *(const float4*)&As[p][kk][ty * 4];
            float4 b4 = *(const float4*)&Bs[p][kk][tx * 4];
            float av[4] = {a4.x, a4.y, a4.z, a4.w};
            float bv[4] = {b4.x, b4.y, b4.z, b4.w};
#pragma unroll
            for (int r = 0; r < 4; r++)
#pragma unroll
                for (int c2 = 0; c2 < 4; c2++)
                    acc[r][c2] += av[r] * bv[c2];
        }
        __syncthreads();
    }

#pragma unroll
    for (int r = 0; r < 4; r++) {
        const int n = n0 + ty * 4 + r;
#pragma unroll
        for (int c2 = 0; c2 < 4; c2++) {
            const int m = m0 + tx * 4 + c2;
            if (m < N) {
                float v = acc[r][c2];
                if (b1) v += b1[m];
                if (b2) v += b2[m];
                if (ACT == 1) v = tanhf(v);
                C[n * ldc + m] = v;
            }
        }
    }
}

// ---------------- fused LSTM step (cp.async double-buffered) -----------------
// Each CTA: 64 batch rows x 64 h-columns x all 4 gates.
// gates[n, g*512+j] = addm[n*ldadd + g*512+j]
//                   + sum_{k<512} h_src[n,k] * Whh[(g*512+j), k]
//                   + sum_{k<25}  A2[n*lda2 + k] * W2[(g*512+j)*ldw2 + k]
// Epilogue applies the LSTM cell update (i,f,g,o torch order).
__global__ void __launch_bounds__(256, 2)
lstm_step_kernel(const float* __restrict__ h_src, const float* __restrict__ c_src,
                 float* __restrict__ h_dst, float* __restrict__ c_dst,
                 const float* __restrict__ Whh, int ldwhh,
                 const float* __restrict__ A2, int lda2,
                 const float* __restrict__ W2, int ldw2,
                 const float* __restrict__ addm, int ldadd) {
    __shared__ __align__(16) float Hs[2][16][68];
    __shared__ __align__(16) float Gs[2][4][16][68];

    const int tid = threadIdx.x;
    const int tx = tid & 15;   // j group
    const int ty = tid >> 4;   // n group
    const int n0 = blockIdx.x * 64;
    const int j0 = blockIdx.y * 64;
    const int lk = tid & 15;
    const int lr = tid >> 4;

    float acc[4][4][4] = {};   // [gate][n][j]

    // ---- small input part: K = 25 (scalar path, buffer 0) ----
    for (int k0 = 0; k0 < FEAT; k0 += 16) {
        const int k = k0 + lk;
        const bool kv = (k < FEAT);
#pragma unroll
        for (int i = 0; i < 4; i++) {
            const int row = lr + 16 * i;
            Hs[0][lk][row] = kv ? A2[(n0 + row) * lda2 + k] : 0.0f;
#pragma unroll
            for (int g = 0; g < 4; g++)
                Gs[0][g][lk][row] = kv ? W2[(g * HID + j0 + row) * ldw2 + k] : 0.0f;
        }
        __syncthreads();
#pragma unroll
        for (int kk = 0; kk < 16; kk++) {
            float4 h4 = *(const float4*)&Hs[0][kk][ty * 4];
            float hv[4] = {h4.x, h4.y, h4.z, h4.w};
#pragma unroll
            for (int g = 0; g < 4; g++) {
                float4 w4 = *(const float4*)&Gs[0][g][kk][tx * 4];
                float wv[4] = {w4.x, w4.y, w4.z, w4.w};
#pragma unroll
                for (int r = 0; r < 4; r++)
#pragma unroll
                    for (int c2 = 0; c2 < 4; c2++)
                        acc[g][r][c2] += hv[r] * wv[c2];
            }
        }
        __syncthreads();
    }

    // ---- recurrent part: K = 512, pipelined ----
    auto issue = [&](int k0, int b) {
#pragma unroll
        for (int i = 0; i < 4; i++) {
            const int row = lr + 16 * i;
            cpa4(s2u(&Hs[b][lk][row]), &h_src[(n0 + row) * HID + k0 + lk]);
#pragma unroll
            for (int g = 0; g < 4; g++)
                cpa4(s2u(&Gs[b][g][lk][row]), &Whh[(g * HID + j0 + row) * ldwhh + k0 + lk]);
        }
        cp_commit();
    };

    issue(0, 0);
    for (int c = 0; c < 32; c++) {
        if (c + 1 < 32) { issue((c + 1) * 16, (c + 1) & 1); cp_wait1(); }
        else            { cp_wait0(); }
        __syncthreads();
        const int p = c & 1;
#pragma unroll
        for (int kk = 0; kk < 16; kk++) {
            float4 h4 = *(const float4*)&Hs[p][kk][ty * 4];
            float hv[4] = {h4.x, h4.y, h4.z, h4.w};
#pragma unroll
            for (int g = 0; g < 4; g++) {
                float4 w4 = *(const float4*)&Gs[p][g][kk][tx * 4];
                float wv[4] = {w4.x, w4.y, w4.z, w4.w};
#pragma unroll
                for (int r = 0; r < 4; r++)
#pragma unroll
                    for (int c2 = 0; c2 < 4; c2++)
                        acc[g][r][c2] += hv[r] * wv[c2];
            }
        }
        __syncthreads();
    }

    // ---- LSTM cell update epilogue ----
#pragma unroll
    for (int r = 0; r < 4; r++) {
        const int n = n0 + ty * 4 + r;
#pragma unroll
        for (int c2 = 0; c2 < 4; c2++) {
            const int j = j0 + tx * 4 + c2;
            const int ab = n * ldadd;
            float iv = acc[0][r][c2] + addm[ab + j];
            float fv = acc[1][r][c2] + addm[ab + 512 + j];
            float gv = acc[2][r][c2] + addm[ab + 1024 + j];
            float ov = acc[3][r][c2] + addm[ab + 1536 + j];
            float cold = c_src[n * HID + j];
            float cn = sigf(fv) * cold + sigf(iv) * tanhf(gv);
            float hn = sigf(ov) * tanhf(cn);
            c_dst[n * HID + j] = cn;
            h_dst[n * HID + j] = hn;
        }
    }
}

// ---------------- fused 3DMM head --------------------------------------------
// coeff[r, m] = b2[m] + sum_j tanh( b1[j] + sum_k pred[r,k]*C1[j,k] ) * C2[m,j]
__global__ void __launch_bounds__(256)
head3dmm_kernel(const float* __restrict__ pred,   // [NROWS, 25]
                const float* __restrict__ C1, const float* __restrict__ b1,
                const float* __restrict__ C2, const float* __restrict__ b2,
                float* __restrict__ coeff) {      // [NROWS, 58]
    __shared__ __align__(16) float sP[64][FEAT + 1];     // pred rows
    __shared__ __align__(16) float sC1c[64][FEAT + 1];   // C1 chunk (64 j-rows x 25)
    __shared__ __align__(16) float sHid[64][64];         // hidden chunk

    const int tid = threadIdx.x;
    const int r0 = blockIdx.x * 64;

    for (int i = tid; i < 64 * FEAT; i += 256) {
        sP[i / FEAT][i % FEAT] = pred[(r0 + i / FEAT) * FEAT + i % FEAT];
    }

    const int row = tid >> 2;
    const int l4 = tid & 3;
    float acc[15];
#pragma unroll
    for (int q = 0; q < 15; q++) acc[q] = 0.0f;

    for (int jc = 0; jc < HID; jc += 64) {
        __syncthreads();
        for (int i = tid; i < 64 * FEAT; i += 256) {
            sC1c[i / FEAT][i % FEAT] = C1[(jc + i / FEAT) * FEAT + i % FEAT];
        }
        __syncthreads();
#pragma unroll
        for (int jj = 0; jj < 16; jj++) {
            const int jl = l4 * 16 + jj;
            float v = b1[jc + jl];
#pragma unroll
            for (int k = 0; k < FEAT; k++)
                v += sP[row][k] * sC1c[jl][k];
            sHid[row][jl] = tanhf(v);
        }
        __syncthreads();
        for (int q = 0; q < 15; q++) {
            const int m = l4 + q * 4;
            if (m < NC3D) {
                float s = 0.0f;
                const float* c2r = C2 + m * HID + jc;
#pragma unroll
                for (int jj = 0; jj < 64; jj++)
                    s += sHid[row][jj] * c2r[jj];
                acc[q] += s;
            }
        }
    }

#pragma unroll
    for (int q = 0; q < 15; q++) {
        const int m = l4 + q * 4;
        if (m < NC3D)
            coeff[(r0 + row) * NC3D + m] = acc[q] + b2[m];
    }
}

// ---------------- host orchestration (graph-capturable) ----------------------
extern "C" void kernel_launch(void* const* d_in, const int* in_sizes, int n_in,
                              void* d_out, int out_size) {
    const float* em   = (const float*)d_in[0];   // listener_emotion (128,750,25)
    const float* eWih = (const float*)d_in[2];
    const float* eWhh = (const float*)d_in[3];
    const float* ebih = (const float*)d_in[4];
    const float* ebhh = (const float*)d_in[5];
    const float* muW  = (const float*)d_in[6];
    const float* mub  = (const float*)d_in[7];
    const float* lvW  = (const float*)d_in[8];
    const float* lvb  = (const float*)d_in[9];
    const float* zW   = (const float*)d_in[10];
    const float* zb   = (const float*)d_in[11];
    const float* dWih = (const float*)d_in[12];
    const float* dWhh = (const float*)d_in[13];
    const float* dbih = (const float*)d_in[14];
    const float* dbhh = (const float*)d_in[15];
    const float* m1W  = (const float*)d_in[16];
    const float* m1b  = (const float*)d_in[17];
    const float* m2W  = (const float*)d_in[18];
    const float* m2b  = (const float*)d_in[19];
    const float* oW   = (const float*)d_in[20];
    const float* ob   = (const float*)d_in[21];
    const float* c1W  = (const float*)d_in[22];
    const float* c1b  = (const float*)d_in[23];
    const float* c2W  = (const float*)d_in[24];
    const float* c2b  = (const float*)d_in[25];

    float* out   = (float*)d_out;
    float* pred  = out;                          // 96000*25
    float* coeff = out + 2400000;                // 96000*58
    float* mu    = out + 2400000 + 5568000;      // 1920*256
    float* lv    = mu + 491520;                  // 1920*256

    float *hbase, *cbase, *hy, *base, *m1, *m2, *encb, *z32;
    cudaGetSymbolAddress((void**)&hbase, g_h);
    cudaGetSymbolAddress((void**)&cbase, g_c);
    cudaGetSymbolAddress((void**)&hy,    g_hy);
    cudaGetSymbolAddress((void**)&base,  g_base);
    cudaGetSymbolAddress((void**)&m1,    g_m1);
    cudaGetSymbolAddress((void**)&m2,    g_m2);
    cudaGetSymbolAddress((void**)&encb,  g_encb);
    cudaGetSymbolAddress((void**)&z32,   g_zero32);
    float* h0 = hbase;
    float* h1 = hbase + BEFF * HID;
    float* c0 = cbase;
    float* c1 = cbase + BEFF * HID;

    const dim3 blk(256);
    const dim3 gLSTM(30, 8);     // 1920/64 x 512/64 (x4 gates per CTA)

    // init
    zero2_kernel<<<256, blk>>>(h0, c0, BEFF * HID);
    addvec_kernel<<<8, blk>>>(ebih, ebhh, encb, GATES);

    // ---- encoder: 50 sequential LSTM steps ----
    for (int t = 0; t < WSTEPS; t++) {
        const float* hs = (t & 1) ? h1 : h0;
        const float* cs = (t & 1) ? c1 : c0;
        float* hd = (t & 1) ? h0 : h1;
        float* cd = (t & 1) ? c0 : c1;
        lstm_step_kernel<<<gLSTM, blk>>>(hs, cs, hd, cd,
                                         eWhh, HID,
                                         em + t * FEAT, WSTEPS * FEAT,   // x_t, row stride 1250
                                         eWih, FEAT,
                                         encb, 0);
    }
    // final h_x lives in h0 (50 steps, even count)

    // ---- latent head ----
    gemm_kernel<0><<<dim3(30, 4), blk>>>(h0, HID, muW, HID, mub, nullptr, mu, ZDIM, ZDIM, HID);
    gemm_kernel<0><<<dim3(30, 4), blk>>>(h0, HID, lvW, HID, lvb, nullptr, lv, ZDIM, ZDIM, HID);
    gemm_kernel<0><<<dim3(30, 8), blk>>>(mu, ZDIM, zW, ZDIM, zb, nullptr, hy, HID, HID, ZDIM);
    // dec_base = h_y @ dec_Wih[:, :512].T + dec_bih + dec_bhh   (hoisted out of loop)
    gemm_kernel<0><<<dim3(30, 32), blk>>>(hy, HID, dWih, HID + FEAT, dbih, dbhh,
                                          base, GATES, GATES, HID);

    // reset state for decoder
    zero2_kernel<<<256, blk>>>(h0, c0, BEFF * HID);

    // ---- decoder: 50 sequential steps ----
    for (int t = 0; t < WSTEPS; t++) {
        const float* hs = (t & 1) ? h1 : h0;
        const float* cs = (t & 1) ? c1 : c0;
        float* hd = (t & 1) ? h0 : h1;
        float* cd = (t & 1) ? c0 : c1;
        const float* yprev = (t == 0) ? z32 : (pred + (t - 1) * FEAT);
        const int ldy = (t == 0) ? 0 : WSTEPS * FEAT;
        lstm_step_kernel<<<gLSTM, blk>>>(hs, cs, hd, cd,
                                         dWhh, HID,
                                         yprev, ldy,
                                         dWih + HID, HID + FEAT,
                                         base, GATES);
        gemm_kernel<1><<<dim3(30, 8), blk>>>(hd, HID, m1W, MDIM, m1b, nullptr, m1, MDIM, MDIM, HID);
        gemm_kernel<1><<<dim3(30, 8), blk>>>(m1, MDIM, m2W, MDIM, m2b, nullptr, m2, MDIM, MDIM, MDIM);
        gemm_kernel<0><<<dim3(30, 1), blk>>>(m2, MDIM, oW, MDIM, ob, nullptr,
                                             pred + t * FEAT, WSTEPS * FEAT, FEAT, MDIM);
    }

    // ---- 3DMM head: fused, no global intermediate ----
    head3dmm_kernel<<<1500, blk>>>(pred, c1W, c1b, c2W, c2b, coeff);
}